// round 3
// baseline (speedup 1.0000x reference)
#include <cuda_runtime.h>
#include <cstdint>

#define NUM_ANCHORS 145152
#define NUM_CH 85
#define IMG_SIZE 1536.0f
#define ROWS_PER_WARP 32
#define WARPS_PER_BLOCK 4
#define THREADS (WARPS_PER_BLOCK * 32)
#define ROWS_PER_BLOCK (ROWS_PER_WARP * WARPS_PER_BLOCK)   // 128

// d_out layout (fp32), matching the reference tuple order, flattened:
//   [0 .. 4N)    bboxes     (N,4) = x0, y0, x1, y1
//   [4N .. 5N)   scores     (N,)
//   [5N .. 6N)   class_pred (N,)  (as float)
//   [6N .. 12N)  detections (N,6) = x0, y0, x1, y1, conf, cls

__device__ __forceinline__ unsigned smem_u32(const void* p) {
    unsigned a;
    asm("{ .reg .u64 t; cvta.to.shared.u64 t, %1; cvt.u32.u64 %0, t; }"
        : "=r"(a) : "l"(p));
    return a;
}

__device__ __forceinline__ void cp_async16(unsigned dst, const void* src) {
    asm volatile("cp.async.cg.shared.global [%0], [%1], 16;"
                 :: "r"(dst), "l"(src));
}

__global__ __launch_bounds__(THREADS)
void yolo_decode_kernel(const float* __restrict__ pred,
                        float* __restrict__ out)
{
    __shared__ float tile[ROWS_PER_BLOCK * NUM_CH];  // 43520 B, 16B-aligned

    const int tid  = threadIdx.x;
    const int warp = tid >> 5;
    const int lane = tid & 31;

    // Each WARP owns 32 contiguous rows: no block-wide barrier anywhere.
    const int row0 = blockIdx.x * ROWS_PER_BLOCK + warp * ROWS_PER_WARP;
    float* wtile = tile + warp * ROWS_PER_WARP * NUM_CH;

    // ---- Stage 32 rows (10880 B = 680 float4) via cp.async, per-warp ----
    // Warp base byte offset = row0*340 which is a multiple of 16 whenever
    // row0 is a multiple of 4 (it is: row0 = 32*k). Fully coalesced.
    {
        const float4* src = (const float4*)(pred + (long long)row0 * NUM_CH);
        unsigned dst0 = smem_u32(wtile);
        const int n4 = ROWS_PER_WARP * NUM_CH / 4;   // 680
        #pragma unroll 6
        for (int j = lane; j < n4; j += 32)
            cp_async16(dst0 + j * 16, src + j);
        asm volatile("cp.async.commit_group;");
        asm volatile("cp.async.wait_group 0;");
        __syncwarp();
    }

    // ---- One thread per anchor; smem row stride 85 (odd) => conflict-free ----
    const float* s = wtile + lane * NUM_CH;
    const int anchor = row0 + lane;

    float cx  = s[0];
    float cy  = s[1];
    float w   = s[2];
    float h   = s[3];
    float obj = s[4];

    // argmax over classes 5..84, lowest index wins ties (strict >)
    float best = s[5];
    int   bi   = 0;
    #pragma unroll
    for (int c = 6; c < NUM_CH; ++c) {
        float v = s[c];
        if (v > best) { best = v; bi = c - 5; }
    }

    // Match reference op order: /IMG_SIZE first, then +/- half.
    float bx = cx / IMG_SIZE;
    float by = cy / IMG_SIZE;
    float bw = w  / IMG_SIZE;
    float bh = h  / IMG_SIZE;
    float x0 = bx - bw * 0.5f;
    float y0 = by - bh * 0.5f;
    float x1 = bx + bw * 0.5f;
    float y1 = by + bh * 0.5f;

    float conf  = best;
    float clsf  = (float)bi;
    float score = obj * conf;

    float* out_sc  = out + (long long)NUM_ANCHORS * 4;
    float* out_cls = out + (long long)NUM_ANCHORS * 5;
    float* out_det = out + (long long)NUM_ANCHORS * 6;

    // Vectorized, coalesced stores.
    ((float4*)out)[anchor] = make_float4(x0, y0, x1, y1);
    out_sc[anchor]  = score;
    out_cls[anchor] = clsf;

    float2* det = (float2*)(out_det + (long long)anchor * 6);
    det[0] = make_float2(x0, y0);
    det[1] = make_float2(x1, y1);
    det[2] = make_float2(conf, clsf);
}

extern "C" void kernel_launch(void* const* d_in, const int* in_sizes, int n_in,
                              void* d_out, int out_size)
{
    const float* pred = (const float*)d_in[0];
    // d_in[1] = score_threshold — unused by the reference computation.
    float* out = (float*)d_out;

    int blocks = NUM_ANCHORS / ROWS_PER_BLOCK;  // 1134
    yolo_decode_kernel<<<blocks, THREADS>>>(pred, out);
}

// round 4
// speedup vs baseline: 1.0201x; 1.0201x over previous
#include <cuda_runtime.h>
#include <cstdint>

#define NUM_ANCHORS 145152
#define NUM_CH 85
#define IMG_SIZE 1536.0f
#define ROWS_PER_TILE 32
#define WARPS_PER_BLOCK 4
#define THREADS (WARPS_PER_BLOCK * 32)
#define NUM_TILES (NUM_ANCHORS / ROWS_PER_TILE)        // 4536
#define TILE_FLOATS (ROWS_PER_TILE * NUM_CH)           // 2720
#define TILE_F4 (TILE_FLOATS / 4)                      // 680
#define BUF_FLOATS (2 * TILE_FLOATS)                   // per-warp double buffer
#define SMEM_BYTES (WARPS_PER_BLOCK * BUF_FLOATS * 4)  // 87040 B

// d_out layout (fp32), reference tuple order, flattened:
//   [0 .. 4N)    bboxes     (N,4) = x0, y0, x1, y1
//   [4N .. 5N)   scores     (N,)
//   [5N .. 6N)   class_pred (N,)  (as float)
//   [6N .. 12N)  detections (N,6) = x0, y0, x1, y1, conf, cls

__device__ __forceinline__ unsigned smem_u32(const void* p) {
    unsigned a;
    asm("{ .reg .u64 t; cvta.to.shared.u64 t, %1; cvt.u32.u64 %0, t; }"
        : "=r"(a) : "l"(p));
    return a;
}

__device__ __forceinline__ void cp_async16(unsigned dst, const void* src) {
    asm volatile("cp.async.cg.shared.global [%0], [%1], 16;"
                 :: "r"(dst), "l"(src));
}

__device__ __forceinline__ void issue_tile_load(unsigned dst0,
                                                const float* __restrict__ pred,
                                                int tile, int lane)
{
    const float4* src = (const float4*)(pred + (long long)tile * TILE_FLOATS);
    #pragma unroll
    for (int j = 0; j < TILE_F4 / 32; ++j)           // 21 full rounds
        cp_async16(dst0 + (lane + j * 32) * 16, src + lane + j * 32);
    // remainder: 680 - 21*32 = 8 elements, lanes 0..7
    if (lane < TILE_F4 - (TILE_F4 / 32) * 32)
        cp_async16(dst0 + (lane + (TILE_F4 / 32) * 32) * 16,
                   src + lane + (TILE_F4 / 32) * 32);
    asm volatile("cp.async.commit_group;");
}

__device__ __forceinline__ void compute_tile(const float* __restrict__ s_base,
                                             float* __restrict__ out,
                                             int tile, int lane)
{
    const float* s = s_base + lane * NUM_CH;   // stride 85 (odd) -> conflict-free
    const int anchor = tile * ROWS_PER_TILE + lane;

    float cx  = s[0];
    float cy  = s[1];
    float w   = s[2];
    float h   = s[3];
    float obj = s[4];

    // argmax over classes 5..84, lowest index wins ties (strict >)
    float best = s[5];
    int   bi   = 0;
    #pragma unroll
    for (int c = 6; c < NUM_CH; ++c) {
        float v = s[c];
        if (v > best) { best = v; bi = c - 5; }
    }

    // Match reference op order: /IMG_SIZE first, then +/- half.
    float bx = cx / IMG_SIZE;
    float by = cy / IMG_SIZE;
    float bw = w  / IMG_SIZE;
    float bh = h  / IMG_SIZE;
    float x0 = bx - bw * 0.5f;
    float y0 = by - bh * 0.5f;
    float x1 = bx + bw * 0.5f;
    float y1 = by + bh * 0.5f;

    float conf  = best;
    float clsf  = (float)bi;
    float score = obj * conf;

    float* out_sc  = out + (long long)NUM_ANCHORS * 4;
    float* out_cls = out + (long long)NUM_ANCHORS * 5;
    float* out_det = out + (long long)NUM_ANCHORS * 6;

    ((float4*)out)[anchor] = make_float4(x0, y0, x1, y1);
    out_sc[anchor]  = score;
    out_cls[anchor] = clsf;

    float2* det = (float2*)(out_det + (long long)anchor * 6);
    det[0] = make_float2(x0, y0);
    det[1] = make_float2(x1, y1);
    det[2] = make_float2(conf, clsf);
}

__global__ __launch_bounds__(THREADS)
void yolo_decode_kernel(const float* __restrict__ pred,
                        float* __restrict__ out,
                        int n_warps_total)
{
    extern __shared__ float smem[];

    const int warp = threadIdx.x >> 5;
    const int lane = threadIdx.x & 31;
    const int wgid = blockIdx.x * WARPS_PER_BLOCK + warp;

    float* buf0 = smem + warp * BUF_FLOATS;
    float* buf1 = buf0 + TILE_FLOATS;
    unsigned dsts[2] = { smem_u32(buf0), smem_u32(buf1) };
    float*   bufs[2] = { buf0, buf1 };

    int tile = wgid;
    if (tile >= NUM_TILES) return;

    // prologue: fill buffer 0
    issue_tile_load(dsts[0], pred, tile, lane);

    int cur = 0;
    int next_tile = tile + n_warps_total;

    while (true) {
        if (next_tile < NUM_TILES) {
            issue_tile_load(dsts[cur ^ 1], pred, next_tile, lane);
            asm volatile("cp.async.wait_group 1;");
        } else {
            asm volatile("cp.async.wait_group 0;");
        }
        __syncwarp();

        compute_tile(bufs[cur], out, tile, lane);

        if (next_tile >= NUM_TILES) break;
        cur ^= 1;
        tile = next_tile;
        next_tile += n_warps_total;
    }
}

extern "C" void kernel_launch(void* const* d_in, const int* in_sizes, int n_in,
                              void* d_out, int out_size)
{
    const float* pred = (const float*)d_in[0];
    // d_in[1] = score_threshold — unused by the reference computation.
    float* out = (float*)d_out;

    cudaFuncSetAttribute(yolo_decode_kernel,
                         cudaFuncAttributeMaxDynamicSharedMemorySize,
                         SMEM_BYTES);

    const int blocks = 296;                       // 2 per SM
    const int n_warps = blocks * WARPS_PER_BLOCK; // 1184
    yolo_decode_kernel<<<blocks, THREADS, SMEM_BYTES>>>(pred, out, n_warps);
}

// round 5
// speedup vs baseline: 1.2149x; 1.1910x over previous
#include <cuda_runtime.h>
#include <cstdint>

#define NUM_ANCHORS 145152
#define NUM_CH 85
#define IMG_SIZE 1536.0f
#define ROWS_PER_TILE 16
#define WARPS_PER_BLOCK 8
#define THREADS (WARPS_PER_BLOCK * 32)
#define NUM_TILES (NUM_ANCHORS / ROWS_PER_TILE)        // 9072
#define TILE_FLOATS (ROWS_PER_TILE * NUM_CH)           // 1360
#define TILE_F4 (TILE_FLOATS / 4)                      // 340
#define BUF_FLOATS (2 * TILE_FLOATS)                   // per-warp double buffer
#define SMEM_BYTES (WARPS_PER_BLOCK * BUF_FLOATS * 4)  // 87040 B

// d_out layout (fp32), reference tuple order, flattened:
//   [0 .. 4N)    bboxes     (N,4) = x0, y0, x1, y1
//   [4N .. 5N)   scores     (N,)
//   [5N .. 6N)   class_pred (N,)  (as float)
//   [6N .. 12N)  detections (N,6) = x0, y0, x1, y1, conf, cls

__device__ __forceinline__ unsigned smem_u32(const void* p) {
    unsigned a;
    asm("{ .reg .u64 t; cvta.to.shared.u64 t, %1; cvt.u32.u64 %0, t; }"
        : "=r"(a) : "l"(p));
    return a;
}

__device__ __forceinline__ void cp_async16(unsigned dst, const void* src) {
    asm volatile("cp.async.cg.shared.global [%0], [%1], 16;"
                 :: "r"(dst), "l"(src));
}

// Stage one 16-row tile (5440 B = 340 float4, contiguous) per warp.
__device__ __forceinline__ void issue_tile_load(unsigned dst0,
                                                const float* __restrict__ pred,
                                                int tile, int lane)
{
    const float4* src = (const float4*)(pred + (long long)tile * TILE_FLOATS);
    #pragma unroll
    for (int j = 0; j < TILE_F4 / 32; ++j)           // 10 full rounds
        cp_async16(dst0 + (lane + j * 32) * 16, src + lane + j * 32);
    if (lane < TILE_F4 - (TILE_F4 / 32) * 32)        // remainder: 20 lanes
        cp_async16(dst0 + (lane + (TILE_F4 / 32) * 32) * 16,
                   src + lane + (TILE_F4 / 32) * 32);
    asm volatile("cp.async.commit_group;");
}

__device__ __forceinline__ void compute_tile(const float* __restrict__ s_base,
                                             float* __restrict__ out,
                                             int tile, int lane)
{
    const unsigned FULL = 0xffffffffu;
    const int row  = lane >> 1;          // 0..15
    const int half = lane & 1;
    const float* s = s_base + row * NUM_CH;     // both pair lanes: SAME row
    const int anchor = tile * ROWS_PER_TILE + row;

    // Header (both lanes read identical values from the shared row).
    float cx  = s[0];
    float cy  = s[1];
    float w   = s[2];
    float h   = s[3];
    float obj = s[4];

    // Split class scan: even lane channels 0..40 (s[5..45]),
    // odd lane channels 39..79 (s[44..84]). 41 iterations each, uniform
    // control flow; 2-channel overlap is harmless for max (tie-break picks
    // the lower index, which is identical for the overlapped channels).
    const int base = 5 + 39 * half;
    float bv = s[base];
    int   bi = base - 5;
    #pragma unroll
    for (int k = 1; k < 41; ++k) {
        float v = s[base + k];
        if (v > bv) { bv = v; bi = base + k - 5; }
    }

    // Combine the two halves (lowest index wins ties).
    float ov = __shfl_xor_sync(FULL, bv, 1);
    int   oi = __shfl_xor_sync(FULL, bi, 1);
    if (ov > bv || (ov == bv && oi < bi)) { bv = ov; bi = oi; }

    // Match reference op order: /IMG_SIZE first, then +/- half.
    float bx = cx / IMG_SIZE;
    float by = cy / IMG_SIZE;
    float bw = w  / IMG_SIZE;
    float bh = h  / IMG_SIZE;
    float x0 = bx - bw * 0.5f;
    float y0 = by - bh * 0.5f;
    float x1 = bx + bw * 0.5f;
    float y1 = by + bh * 0.5f;

    float conf  = bv;
    float clsf  = (float)bi;
    float score = obj * conf;

    float* out_sc  = out + (long long)NUM_ANCHORS * 4;
    float* out_cls = out + (long long)NUM_ANCHORS * 5;
    float* out_det = out + (long long)NUM_ANCHORS * 6;

    if (half == 0) {
        // 16 even lanes: contiguous float4 (256 B/warp) + scalar streams.
        ((float4*)out)[anchor] = make_float4(x0, y0, x1, y1);
        out_sc[anchor]  = score;
        out_cls[anchor] = clsf;
    } else {
        // 16 odd lanes: detections, 3x float2, 384 B contiguous per warp.
        float2* det = (float2*)(out_det + (long long)anchor * 6);
        det[0] = make_float2(x0, y0);
        det[1] = make_float2(x1, y1);
        det[2] = make_float2(conf, clsf);
    }
}

__global__ __launch_bounds__(THREADS)
void yolo_decode_kernel(const float* __restrict__ pred,
                        float* __restrict__ out,
                        int n_warps_total)
{
    extern __shared__ float smem[];

    const int warp = threadIdx.x >> 5;
    const int lane = threadIdx.x & 31;
    const int wgid = blockIdx.x * WARPS_PER_BLOCK + warp;

    float* buf0 = smem + warp * BUF_FLOATS;
    float* buf1 = buf0 + TILE_FLOATS;
    unsigned dsts[2] = { smem_u32(buf0), smem_u32(buf1) };
    float*   bufs[2] = { buf0, buf1 };

    int tile = wgid;
    if (tile >= NUM_TILES) return;

    // prologue: fill buffer 0
    issue_tile_load(dsts[0], pred, tile, lane);

    int cur = 0;
    int next_tile = tile + n_warps_total;

    while (true) {
        if (next_tile < NUM_TILES) {
            issue_tile_load(dsts[cur ^ 1], pred, next_tile, lane);
            asm volatile("cp.async.wait_group 1;");
        } else {
            asm volatile("cp.async.wait_group 0;");
        }
        __syncwarp();

        compute_tile(bufs[cur], out, tile, lane);

        if (next_tile >= NUM_TILES) break;
        cur ^= 1;
        tile = next_tile;
        next_tile += n_warps_total;
    }
}

extern "C" void kernel_launch(void* const* d_in, const int* in_sizes, int n_in,
                              void* d_out, int out_size)
{
    const float* pred = (const float*)d_in[0];
    // d_in[1] = score_threshold — unused by the reference computation.
    float* out = (float*)d_out;

    cudaFuncSetAttribute(yolo_decode_kernel,
                         cudaFuncAttributeMaxDynamicSharedMemorySize,
                         SMEM_BYTES);

    const int blocks = 296;                        // 2 per SM, persistent
    const int n_warps = blocks * WARPS_PER_BLOCK;  // 2368
    yolo_decode_kernel<<<blocks, THREADS, SMEM_BYTES>>>(pred, out, n_warps);
}